// round 12
// baseline (speedup 1.0000x reference)
// AttLayer fused, GB300 (sm_103 PTX: mma.sync tf32 + cp.async).
// out[b,d] = sum_t exp(tanh(x@W + b)·uw)_t * x[b,t,d] / (sum_t exp(...) + eps)
// R9: combine R8 (zero-CVT mainloop, W pre-converted+pre-swizzled to fragment
//     order by prep kernel) with R6 (TILE_T=64 -> ~102KB SMEM -> 2 CTAs/SM).
//     W chunk granularity KC=16 (4096-word linear blocks). Warp tile M=16,N=64,
//     __launch_bounds__(512,2) forces <=64 regs.

#include <cuda_runtime.h>
#include <cstdint>
#include <math.h>

#define DEV __device__ __forceinline__

static constexpr int BATCH  = 64;
static constexpr int TLEN   = 2048;
static constexpr int DIM    = 256;
static constexpr int TILE_T = 64;
static constexpr int NTILES = TLEN / TILE_T;   // 32
static constexpr int KC     = 16;              // K per chunk
static constexpr int NCHUNK = DIM / KC;        // 16
static constexpr int WCHUNK_F = 128 * 32;      // 4096 words = 16KB per chunk

static constexpr int XSTR   = 260;             // A-frag LDS conflict-free

// SMEM layout (bytes)
static constexpr int SMEM_BIAS = 0;                              // 256 f
static constexpr int SMEM_UW   = 1024;                           // 256 f
static constexpr int SMEM_EP   = 2048;                           // 64*4 f
static constexpr int SMEM_WEXP = 3072;                           // 64 f
static constexpr int SMEM_FLAG = 3328;                           // int
static constexpr int SMEM_X    = 3584;
static constexpr int X_BYTES   = TILE_T * XSTR * 4;              // 66560
static constexpr int SMEM_W    = SMEM_X + X_BYTES;               // 70144
static constexpr int SMEM_TOTAL = SMEM_W + 2 * WCHUNK_F * 4;     // 102912 (~100.5KB)

__device__ uint32_t g_Wtf[DIM * DIM];          // fragment-order tf32 W (256KB)
__device__ float g_partial[BATCH * NTILES * DIM];
__device__ float g_S[BATCH * NTILES];
__device__ int   g_cnt[BATCH];                 // zero-init; reset by reducer

DEV uint32_t smem_u32(const void* p) {
    uint32_t a;
    asm("{ .reg .u64 t; cvta.to.shared.u64 t, %1; cvt.u32.u64 %0, t; }"
        : "=r"(a) : "l"(p));
    return a;
}
DEV void cp16(uint32_t saddr, const void* g) {
    asm volatile("cp.async.cg.shared.global [%0], [%1], 16;"
                 :: "r"(saddr), "l"(g) : "memory");
}
DEV void cp_commit() { asm volatile("cp.async.commit_group;" ::: "memory"); }
template <int N> DEV void cp_wait() {
    asm volatile("cp.async.wait_group %0;" :: "n"(N) : "memory");
}
DEV uint32_t f2tf(float f) {
    uint32_t r;
    asm("cvt.rna.tf32.f32 %0, %1;" : "=r"(r) : "f"(f));
    return r;
}
DEV void mma_tf32(float* d, uint32_t a0, uint32_t a1, uint32_t a2, uint32_t a3,
                  uint32_t b0, uint32_t b1) {
    asm volatile(
        "mma.sync.aligned.m16n8k8.row.col.f32.tf32.tf32.f32 "
        "{%0,%1,%2,%3}, {%4,%5,%6,%7}, {%8,%9}, {%0,%1,%2,%3};"
        : "+f"(d[0]), "+f"(d[1]), "+f"(d[2]), "+f"(d[3])
        : "r"(a0), "r"(a1), "r"(a2), "r"(a3), "r"(b0), "r"(b1));
}

// ---- prep: W[k][n] fp32 -> g_Wtf fragment-order tf32, KC=16 chunk blocks ----
// c = k>>4; kk=k&15: s=kk>>3 (0..1), h=(kk>>2)&1, tg2=kk&3
// n: q=n>>6, j=(n>>3)&7, gg=n&7
// row = ((s*2+h)*8+gg)*4 + tg2 (0..127); col = (q*8 + j + 16*(gg&1) + 4*tg2) & 31
__global__ void __launch_bounds__(512, 4)
w_prep(const float* __restrict__ W) {
    int i = blockIdx.x * 512 + threadIdx.x;    // 0..65535
    int k = i >> 8, n = i & 255;
    int c = k >> 4, kk = k & 15;
    int s = kk >> 3, h = (kk >> 2) & 1, tg2 = kk & 3;
    int q = n >> 6, j = (n >> 3) & 7, gg = n & 7;
    int r   = ((s * 2 + h) * 8 + gg) * 4 + tg2;
    int col = (q * 8 + j + 16 * (gg & 1) + 4 * tg2) & 31;
    g_Wtf[c * WCHUNK_F + r * 32 + col] = f2tf(W[k * DIM + n]);
}

DEV void load_w_chunk(uint32_t sb, int c, int buf, int tid) {
    // linear 16KB copy: 1024 uint4 / 512 threads = 2 each
    const uint32_t* src = g_Wtf + c * WCHUNK_F;
    const uint32_t dst = sb + (uint32_t)(SMEM_W + buf * WCHUNK_F * 4);
    #pragma unroll
    for (int r = 0; r < 2; ++r) {
        int i = tid + r * 512;
        cp16(dst + (uint32_t)i * 16, src + i * 4);
    }
    cp_commit();
}

__global__ void __launch_bounds__(512, 2)
att_fused(const float* __restrict__ x,
          const float* __restrict__ bvec, const float* __restrict__ uw,
          const int* __restrict__ mask, float* __restrict__ out) {
    extern __shared__ char smem[];
    float* sf = (float*)smem;
    const uint32_t sb = smem_u32(smem);

    const int tid = threadIdx.x;
    const int wid = tid >> 5;
    const int lid = tid & 31;
    const int wm  = wid >> 2;            // 0..3 : rows wm*16..+15
    const int wn  = wid & 3;             // 0..3 : cols wn*64..+63
    const int g   = lid >> 2;            // 0..7
    const int tg  = lid & 3;             // 0..3

    const int bt = blockIdx.x;           // 0..2047
    const int b  = bt >> 5;
    const int t0 = (bt & 31) * TILE_T;

    if (tid < 256) {
        sf[SMEM_BIAS / 4 + tid] = bvec[tid];
        sf[SMEM_UW / 4 + tid]   = uw[tid];
    }

    // ---- prologue: cp.async W0 | x fill (LDG->CVT->STS) | cp.async W1 ----
    load_w_chunk(sb, 0, 0, tid);

    const float* xrow = x + ((size_t)b * TLEN + t0) * DIM;
    float* xs = sf + SMEM_X / 4;
    #pragma unroll
    for (int r = 0; r < 8; ++r) {        // 64*64=4096 float4 / 512 thr
        int i = r * 512 + tid;
        int m = i >> 6, d0 = (i & 63) * 4;
        float4 v = *(const float4*)(xrow + (size_t)m * DIM + d0);
        uint4 uv;
        uv.x = f2tf(v.x); uv.y = f2tf(v.y); uv.z = f2tf(v.z); uv.w = f2tf(v.w);
        *(uint4*)(xs + m * XSTR + d0) = uv;
    }
    load_w_chunk(sb, 1, 1, tid);
    cp_wait<1>();                        // W0 ready
    __syncthreads();

    // ---- mainloop: warp tile M=16, N=64; zero CVTs ----
    float acc[8][4];
    #pragma unroll
    for (int j = 0; j < 8; ++j)
        #pragma unroll
        for (int r = 0; r < 4; ++r) acc[j][r] = 0.f;

    const uint32_t* xu = (const uint32_t*)xs;
    const int arow = wm * 16 + g;
    const int colb  = (wn * 8 + 16 * (g & 1) + 4 * tg) & 31;
    const int colb4 = (colb + 4) & 31;

    for (int c = 0; c < NCHUNK; ++c) {
        const uint32_t* wbu =
            (const uint32_t*)(sf + SMEM_W / 4 + (c & 1) * WCHUNK_F);
        #pragma unroll
        for (int s = 0; s < 2; ++s) {    // KC=16 -> 2 k8 steps
            const uint32_t* ar = xu + arow * XSTR + c * KC + s * 8 + tg;
            uint32_t a0 = ar[0];
            uint32_t a1 = ar[8 * XSTR];
            uint32_t a2 = ar[4];
            uint32_t a3 = ar[8 * XSTR + 4];
            uint32_t bfr[8][2];
            #pragma unroll
            for (int h = 0; h < 2; ++h) {
                int r = ((s * 2 + h) * 8 + g) * 4 + tg;
                uint4 v0 = *(const uint4*)(wbu + r * 32 + colb);
                uint4 v1 = *(const uint4*)(wbu + r * 32 + colb4);
                bfr[0][h] = v0.x; bfr[1][h] = v0.y; bfr[2][h] = v0.z; bfr[3][h] = v0.w;
                bfr[4][h] = v1.x; bfr[5][h] = v1.y; bfr[6][h] = v1.z; bfr[7][h] = v1.w;
            }
            #pragma unroll
            for (int j = 0; j < 8; ++j)
                mma_tf32(acc[j], a0, a1, a2, a3, bfr[j][0], bfr[j][1]);
        }
        __syncthreads();                 // done reading buf c&1
        if (c + 2 < NCHUNK) {
            load_w_chunk(sb, c + 2, c & 1, tid);
            cp_wait<1>();                // chunk c+1 ready
            __syncthreads();
        } else if (c + 1 < NCHUNK) {
            cp_wait<0>();
            __syncthreads();
        }
    }

    // ---- epilogue 1: eij partials ----
    {
        const float* sBias = sf + SMEM_BIAS / 4;
        const float* sUw   = sf + SMEM_UW / 4;
        float* epart       = sf + SMEM_EP / 4;
        float rs0 = 0.f, rs1 = 0.f;
        #pragma unroll
        for (int j = 0; j < 8; ++j) {
            const int c0 = wn * 64 + j * 8 + 2 * tg;
            const float b0 = sBias[c0], b1 = sBias[c0 + 1];
            const float u0 = sUw[c0],   u1 = sUw[c0 + 1];
            rs0 += tanhf(acc[j][0] + b0) * u0 + tanhf(acc[j][1] + b1) * u1;
            rs1 += tanhf(acc[j][2] + b0) * u0 + tanhf(acc[j][3] + b1) * u1;
        }
        rs0 += __shfl_xor_sync(0xFFFFFFFFu, rs0, 1);
        rs0 += __shfl_xor_sync(0xFFFFFFFFu, rs0, 2);
        rs1 += __shfl_xor_sync(0xFFFFFFFFu, rs1, 1);
        rs1 += __shfl_xor_sync(0xFFFFFFFFu, rs1, 2);
        if (tg == 0) {
            const int r = wm * 16 + g;
            epart[r * 4 + wn]       = rs0;
            epart[(r + 8) * 4 + wn] = rs1;
        }
    }
    __syncthreads();

    // ---- epilogue 2: softmax-numerator weights ----
    float* sWexp = sf + SMEM_WEXP / 4;
    if (tid < TILE_T) {
        const float* epart = sf + SMEM_EP / 4;
        float e = epart[tid * 4 + 0] + epart[tid * 4 + 1] +
                  epart[tid * 4 + 2] + epart[tid * 4 + 3];
        sWexp[tid] = expf(e) * (float)mask[(size_t)b * TLEN + t0 + tid];
    }
    __syncthreads();

    if (tid == 0) {
        float s = 0.f;
        #pragma unroll 8
        for (int m = 0; m < TILE_T; ++m) s += sWexp[m];
        g_S[bt] = s;
    }

    // ---- epilogue 3: weighted column sum from resident x tile (tf32 values) ----
    if (tid < DIM) {
        float a0 = 0.f;
        #pragma unroll 8
        for (int m = 0; m < TILE_T; ++m)
            a0 = fmaf(sWexp[m], xs[m * XSTR + tid], a0);
        g_partial[(size_t)bt * DIM + tid] = a0;
    }

    // ---- fused tail: last CTA of each batch reduces (deterministic order) ----
    __threadfence();
    __syncthreads();
    int* sflag = (int*)(smem + SMEM_FLAG);
    if (tid == 0) {
        int old = atomicAdd(&g_cnt[b], 1);
        *sflag = (old == NTILES - 1);
    }
    __syncthreads();
    if (*sflag) {
        __threadfence();   // acquire: see all tiles' partials
        if (tid < DIM) {
            float s = 0.f, p = 0.f;
            #pragma unroll
            for (int t = 0; t < NTILES; ++t) {
                p += g_partial[(size_t)(b * NTILES + t) * DIM + tid];
                s += g_S[b * NTILES + t];
            }
            out[b * DIM + tid] = p / (s + 1e-7f);
        }
        if (tid == 0) g_cnt[b] = 0;   // reset for next graph replay
    }
}

extern "C" void kernel_launch(void* const* d_in, const int* in_sizes, int n_in,
                              void* d_out, int out_size) {
    const float* x    = (const float*)d_in[0];
    const float* W    = (const float*)d_in[1];
    const float* bvec = (const float*)d_in[2];
    const float* uw   = (const float*)d_in[3];
    const int*   mask = (const int*)d_in[4];
    float* out = (float*)d_out;

    w_prep<<<DIM * DIM / 512, 512>>>(W);
    cudaFuncSetAttribute(att_fused, cudaFuncAttributeMaxDynamicSharedMemorySize,
                         SMEM_TOTAL);
    att_fused<<<BATCH * NTILES, 512, SMEM_TOTAL>>>(x, bvec, uw, mask, out);
}

// round 13
// speedup vs baseline: 1.1249x; 1.1249x over previous
// AttLayer fused, GB300 (sm_103 PTX: mma.sync tf32 + cp.async).
// out[b,d] = sum_t exp(tanh(x@W + b)·uw)_t * x[b,t,d] / (sum_t exp(...) + eps)
// R12: TILE_T=64 with 256 threads / 8 warps, warp tile M=32 N=64 (R8's proven
//      shape) -> SAME total LDS traffic as R8 but 2 CTAs/SM for cross-CTA
//      latency hiding. Zero-CVT mainloop; W pre-swizzled (KC=16 blocks) in gmem.

#include <cuda_runtime.h>
#include <cstdint>
#include <math.h>

#define DEV __device__ __forceinline__

static constexpr int BATCH  = 64;
static constexpr int TLEN   = 2048;
static constexpr int DIM    = 256;
static constexpr int TILE_T = 64;
static constexpr int NTILES = TLEN / TILE_T;   // 32
static constexpr int KC     = 16;              // K per chunk
static constexpr int NCHUNK = DIM / KC;        // 16
static constexpr int WCHUNK_F = 128 * 32;      // 4096 words = 16KB per chunk
static constexpr int NTHR   = 256;             // 8 warps

static constexpr int XSTR   = 260;             // A-frag LDS conflict-free

// SMEM layout (bytes)
static constexpr int SMEM_BIAS = 0;                              // 256 f
static constexpr int SMEM_UW   = 1024;                           // 256 f
static constexpr int SMEM_EP   = 2048;                           // 64*4 f
static constexpr int SMEM_WEXP = 3072;                           // 64 f
static constexpr int SMEM_FLAG = 3328;                           // int
static constexpr int SMEM_X    = 3584;
static constexpr int X_BYTES   = TILE_T * XSTR * 4;              // 66560
static constexpr int SMEM_W    = SMEM_X + X_BYTES;               // 70144
static constexpr int SMEM_TOTAL = SMEM_W + 2 * WCHUNK_F * 4;     // 102912

__device__ uint32_t g_Wtf[DIM * DIM];          // fragment-order tf32 W (256KB)
__device__ float g_partial[BATCH * NTILES * DIM];
__device__ float g_S[BATCH * NTILES];
__device__ int   g_cnt[BATCH];                 // zero-init; reset by reducer

DEV uint32_t smem_u32(const void* p) {
    uint32_t a;
    asm("{ .reg .u64 t; cvta.to.shared.u64 t, %1; cvt.u32.u64 %0, t; }"
        : "=r"(a) : "l"(p));
    return a;
}
DEV void cp16(uint32_t saddr, const void* g) {
    asm volatile("cp.async.cg.shared.global [%0], [%1], 16;"
                 :: "r"(saddr), "l"(g) : "memory");
}
DEV void cp_commit() { asm volatile("cp.async.commit_group;" ::: "memory"); }
template <int N> DEV void cp_wait() {
    asm volatile("cp.async.wait_group %0;" :: "n"(N) : "memory");
}
DEV uint32_t f2tf(float f) {
    uint32_t r;
    asm("cvt.rna.tf32.f32 %0, %1;" : "=r"(r) : "f"(f));
    return r;
}
DEV void mma_tf32(float* d, uint32_t a0, uint32_t a1, uint32_t a2, uint32_t a3,
                  uint32_t b0, uint32_t b1) {
    asm volatile(
        "mma.sync.aligned.m16n8k8.row.col.f32.tf32.tf32.f32 "
        "{%0,%1,%2,%3}, {%4,%5,%6,%7}, {%8,%9}, {%0,%1,%2,%3};"
        : "+f"(d[0]), "+f"(d[1]), "+f"(d[2]), "+f"(d[3])
        : "r"(a0), "r"(a1), "r"(a2), "r"(a3), "r"(b0), "r"(b1));
}

// ---- prep: W[k][n] fp32 -> g_Wtf fragment-order tf32, KC=16 chunk blocks ----
// c = k>>4; kk=k&15: s=kk>>3, h=(kk>>2)&1, tg2=kk&3
// n: q=n>>6, j=(n>>3)&7, gg=n&7
// row = ((s*2+h)*8+gg)*4 + tg2 (0..127); col = (q*8 + j + 16*(gg&1) + 4*tg2) & 31
__global__ void __launch_bounds__(512, 4)
w_prep(const float* __restrict__ W) {
    int i = blockIdx.x * 512 + threadIdx.x;    // 0..65535
    int k = i >> 8, n = i & 255;
    int c = k >> 4, kk = k & 15;
    int s = kk >> 3, h = (kk >> 2) & 1, tg2 = kk & 3;
    int q = n >> 6, j = (n >> 3) & 7, gg = n & 7;
    int r   = ((s * 2 + h) * 8 + gg) * 4 + tg2;
    int col = (q * 8 + j + 16 * (gg & 1) + 4 * tg2) & 31;
    g_Wtf[c * WCHUNK_F + r * 32 + col] = f2tf(W[k * DIM + n]);
}

DEV void load_w_chunk(uint32_t sb, int c, int buf, int tid) {
    // linear 16KB copy: 1024 uint4 / 256 threads = 4 each
    const uint32_t* src = g_Wtf + c * WCHUNK_F;
    const uint32_t dst = sb + (uint32_t)(SMEM_W + buf * WCHUNK_F * 4);
    #pragma unroll
    for (int r = 0; r < 4; ++r) {
        int i = tid + r * NTHR;
        cp16(dst + (uint32_t)i * 16, src + i * 4);
    }
    cp_commit();
}

__global__ void __launch_bounds__(NTHR, 2)
att_fused(const float* __restrict__ x,
          const float* __restrict__ bvec, const float* __restrict__ uw,
          const int* __restrict__ mask, float* __restrict__ out) {
    extern __shared__ char smem[];
    float* sf = (float*)smem;
    const uint32_t sb = smem_u32(smem);

    const int tid = threadIdx.x;
    const int wid = tid >> 5;            // 0..7
    const int lid = tid & 31;
    const int wm  = wid >> 2;            // 0..1 : rows wm*32..+31
    const int wn  = wid & 3;             // 0..3 : cols wn*64..+63
    const int g   = lid >> 2;            // 0..7
    const int tg  = lid & 3;             // 0..3

    const int bt = blockIdx.x;           // 0..2047
    const int b  = bt >> 5;
    const int t0 = (bt & 31) * TILE_T;

    sf[SMEM_BIAS / 4 + tid] = bvec[tid];
    sf[SMEM_UW / 4 + tid]   = uw[tid];

    // ---- prologue: cp.async W0 | x fill (LDG->CVT->STS) | cp.async W1 ----
    load_w_chunk(sb, 0, 0, tid);

    const float* xrow = x + ((size_t)b * TLEN + t0) * DIM;
    float* xs = sf + SMEM_X / 4;
    #pragma unroll
    for (int r = 0; r < 16; ++r) {       // 64*64=4096 float4 / 256 thr
        int i = r * NTHR + tid;
        int m = i >> 6, d0 = (i & 63) * 4;
        float4 v = *(const float4*)(xrow + (size_t)m * DIM + d0);
        uint4 uv;
        uv.x = f2tf(v.x); uv.y = f2tf(v.y); uv.z = f2tf(v.z); uv.w = f2tf(v.w);
        *(uint4*)(xs + m * XSTR + d0) = uv;
    }
    load_w_chunk(sb, 1, 1, tid);
    cp_wait<1>();                        // W0 ready
    __syncthreads();

    // ---- mainloop: warp tile M=32, N=64; zero CVTs ----
    float acc[2][8][4];
    #pragma unroll
    for (int i = 0; i < 2; ++i)
        #pragma unroll
        for (int j = 0; j < 8; ++j)
            #pragma unroll
            for (int r = 0; r < 4; ++r) acc[i][j][r] = 0.f;

    const uint32_t* xu = (const uint32_t*)xs;
    const int arow0 = wm * 32 + g;
    const int colb  = (wn * 8 + 16 * (g & 1) + 4 * tg) & 31;
    const int colb4 = (colb + 4) & 31;

    for (int c = 0; c < NCHUNK; ++c) {
        const uint32_t* wbu =
            (const uint32_t*)(sf + SMEM_W / 4 + (c & 1) * WCHUNK_F);
        #pragma unroll
        for (int s = 0; s < 2; ++s) {    // KC=16 -> 2 k8 steps
            uint32_t a[2][4];
            #pragma unroll
            for (int i = 0; i < 2; ++i) {
                const uint32_t* ar = xu + (arow0 + i * 16) * XSTR + c * KC + s * 8 + tg;
                a[i][0] = ar[0];
                a[i][1] = ar[8 * XSTR];
                a[i][2] = ar[4];
                a[i][3] = ar[8 * XSTR + 4];
            }
            uint32_t bfr[8][2];
            #pragma unroll
            for (int h = 0; h < 2; ++h) {
                int r = ((s * 2 + h) * 8 + g) * 4 + tg;
                uint4 v0 = *(const uint4*)(wbu + r * 32 + colb);
                uint4 v1 = *(const uint4*)(wbu + r * 32 + colb4);
                bfr[0][h] = v0.x; bfr[1][h] = v0.y; bfr[2][h] = v0.z; bfr[3][h] = v0.w;
                bfr[4][h] = v1.x; bfr[5][h] = v1.y; bfr[6][h] = v1.z; bfr[7][h] = v1.w;
            }
            #pragma unroll
            for (int i = 0; i < 2; ++i)
                #pragma unroll
                for (int j = 0; j < 8; ++j)
                    mma_tf32(acc[i][j], a[i][0], a[i][1], a[i][2], a[i][3],
                             bfr[j][0], bfr[j][1]);
        }
        __syncthreads();                 // done reading buf c&1
        if (c + 2 < NCHUNK) {
            load_w_chunk(sb, c + 2, c & 1, tid);
            cp_wait<1>();                // chunk c+1 ready
            __syncthreads();
        } else if (c + 1 < NCHUNK) {
            cp_wait<0>();
            __syncthreads();
        }
    }

    // ---- epilogue 1: eij partials ----
    {
        const float* sBias = sf + SMEM_BIAS / 4;
        const float* sUw   = sf + SMEM_UW / 4;
        float* epart       = sf + SMEM_EP / 4;
        #pragma unroll
        for (int i = 0; i < 2; ++i) {
            float rs0 = 0.f, rs1 = 0.f;
            #pragma unroll
            for (int j = 0; j < 8; ++j) {
                const int c0 = wn * 64 + j * 8 + 2 * tg;
                const float b0 = sBias[c0], b1 = sBias[c0 + 1];
                const float u0 = sUw[c0],   u1 = sUw[c0 + 1];
                rs0 += tanhf(acc[i][j][0] + b0) * u0 + tanhf(acc[i][j][1] + b1) * u1;
                rs1 += tanhf(acc[i][j][2] + b0) * u0 + tanhf(acc[i][j][3] + b1) * u1;
            }
            rs0 += __shfl_xor_sync(0xFFFFFFFFu, rs0, 1);
            rs0 += __shfl_xor_sync(0xFFFFFFFFu, rs0, 2);
            rs1 += __shfl_xor_sync(0xFFFFFFFFu, rs1, 1);
            rs1 += __shfl_xor_sync(0xFFFFFFFFu, rs1, 2);
            if (tg == 0) {
                const int r = wm * 32 + i * 16 + g;
                epart[r * 4 + wn]       = rs0;
                epart[(r + 8) * 4 + wn] = rs1;
            }
        }
    }
    __syncthreads();

    // ---- epilogue 2: softmax-numerator weights ----
    float* sWexp = sf + SMEM_WEXP / 4;
    if (tid < TILE_T) {
        const float* epart = sf + SMEM_EP / 4;
        float e = epart[tid * 4 + 0] + epart[tid * 4 + 1] +
                  epart[tid * 4 + 2] + epart[tid * 4 + 3];
        sWexp[tid] = expf(e) * (float)mask[(size_t)b * TLEN + t0 + tid];
    }
    __syncthreads();

    if (tid == 0) {
        float s = 0.f;
        #pragma unroll 8
        for (int m = 0; m < TILE_T; ++m) s += sWexp[m];
        g_S[bt] = s;
    }

    // ---- epilogue 3: weighted column sum from resident x tile (tf32 values) ----
    {
        float a0 = 0.f;
        #pragma unroll 8
        for (int m = 0; m < TILE_T; ++m)
            a0 = fmaf(sWexp[m], xs[m * XSTR + tid], a0);
        g_partial[(size_t)bt * DIM + tid] = a0;
    }

    // ---- fused tail: last CTA of each batch reduces (deterministic order) ----
    __threadfence();
    __syncthreads();
    int* sflag = (int*)(smem + SMEM_FLAG);
    if (tid == 0) {
        int old = atomicAdd(&g_cnt[b], 1);
        *sflag = (old == NTILES - 1);
    }
    __syncthreads();
    if (*sflag) {
        __threadfence();   // acquire: see all tiles' partials
        float s = 0.f, p = 0.f;
        #pragma unroll
        for (int t = 0; t < NTILES; ++t) {
            p += g_partial[(size_t)(b * NTILES + t) * DIM + tid];
            s += g_S[b * NTILES + t];
        }
        out[b * DIM + tid] = p / (s + 1e-7f);
        if (tid == 0) g_cnt[b] = 0;   // reset for next graph replay
    }
}

extern "C" void kernel_launch(void* const* d_in, const int* in_sizes, int n_in,
                              void* d_out, int out_size) {
    const float* x    = (const float*)d_in[0];
    const float* W    = (const float*)d_in[1];
    const float* bvec = (const float*)d_in[2];
    const float* uw   = (const float*)d_in[3];
    const int*   mask = (const int*)d_in[4];
    float* out = (float*)d_out;

    w_prep<<<DIM * DIM / 512, 512>>>(W);
    cudaFuncSetAttribute(att_fused, cudaFuncAttributeMaxDynamicSharedMemorySize,
                         SMEM_TOTAL);
    att_fused<<<BATCH * NTILES, NTHR, SMEM_TOTAL>>>(x, bvec, uw, mask, out);
}